// round 16
// baseline (speedup 1.0000x reference)
#include <cuda_runtime.h>
#include <cuda_fp16.h>
#include <cstdint>

#define NROWS 12000     // B*T = 8*1500
#define MPAD  12032     // 94 * 128
#define BDIMB 8
#define TDIM  1500
#define CDIM  512
#define VCNT  4096
#define KSEL  100
#define DELTA 0.25f     // exact-rescue window on approx d^2 (~25 sigma of fp16 GEMM error)
#define LCAP  32

// ---- mma.sync GEMM tiling (fp16 single-term) ----
#define BM 128
#define BN 128
#define BK 32
#define ROWB 80                       // smem leading dim bytes (40 halfs), ldmatrix conflict-free
#define OPBYTES (128 * ROWB)          // 10240 per operand per stage
#define STG (2 * OPBYTES)             // 20480 (A, B)
#define NSTAGE 4
#define SMEM_GEMM (NSTAGE * STG)      // 81920 -> 2 CTAs/SM
#define NKIT (CDIM / BK)              // 16

// ---------------- scratch (device globals: no allocations allowed) ----------------
__device__ __align__(16) float g_E[(size_t)NROWS * CDIM];      // fp32 tokens x C (exact path)
__device__ __align__(16) __half g_Eh[(size_t)MPAD * CDIM];     // rows >= NROWS stay 0
__device__ __align__(16) __half g_Bh[(size_t)VCNT * CDIM];
__device__ float g_esq[NROWS];
__device__ float g_csq[VCNT];
__device__ __align__(16) float g_D2[(size_t)NROWS * VCNT];     // 196.6 MB approx d^2
__device__ int   g_is64;
__device__ float g_row_loss[NROWS];
__device__ float g_row_match[NROWS];

// ---------------- helpers ----------------
__device__ __forceinline__ float warpSumF(float v) {
    #pragma unroll
    for (int o = 16; o > 0; o >>= 1) v += __shfl_down_sync(0xffffffffu, v, o);
    return v;
}
__device__ __forceinline__ uint32_t smem_u32(const void* p) {
    uint32_t a;
    asm("{ .reg .u64 t; cvta.to.shared.u64 t, %1; cvt.u32.u64 %0, t; }" : "=r"(a) : "l"(p));
    return a;
}
__device__ __forceinline__ void cp16(uint32_t dst, const void* src) {
    asm volatile("cp.async.cg.shared.global [%0], [%1], 16;" :: "r"(dst), "l"(src));
}
#define LDSM4(r, a) \
    asm volatile("ldmatrix.sync.aligned.m8n8.x4.shared.b16 {%0,%1,%2,%3}, [%4];" \
        : "=r"((r)[0]), "=r"((r)[1]), "=r"((r)[2]), "=r"((r)[3]) : "r"(a))

__device__ __forceinline__ void mma16816(float* c, const uint32_t* a, const uint32_t* b) {
    asm volatile(
        "mma.sync.aligned.m16n8k16.row.col.f32.f16.f16.f32 "
        "{%0,%1,%2,%3}, {%4,%5,%6,%7}, {%8,%9}, {%0,%1,%2,%3};"
        : "+f"(c[0]), "+f"(c[1]), "+f"(c[2]), "+f"(c[3])
        : "r"(a[0]), "r"(a[1]), "r"(a[2]), "r"(a[3]), "r"(b[0]), "r"(b[1]));
}

// warp-aggregated histogram add: lanes sharing `bin` elect a leader which adds
// popc(group) once. Identical counts to per-lane atomicAdd; ~32x fewer ATOMS
// instructions on degenerate bins, few-lane atomics on spread bins.
__device__ __forceinline__ void hist_add(unsigned* hist, unsigned bin, bool part, int lane) {
    unsigned tagged = part ? bin : 0xFFFFFFFFu;
    unsigned m = __match_any_sync(0xffffffffu, tagged);
    if (part && ((m & ((1u << lane) - 1u)) == 0u))   // lowest participating lane of group
        atomicAdd(&hist[bin], (unsigned)__popc(m));
}

// ---------------- transpose student_emb (B,C,T) -> g_E fp32 + g_Eh fp16 ----------------
__global__ void k_transpose(const float* __restrict__ se) {
    __shared__ float tile[32][33];
    int b  = blockIdx.z;
    int t0 = blockIdx.x * 32;
    int c0 = blockIdx.y * 32;
    const float* src = se + (size_t)b * CDIM * TDIM;
    #pragma unroll
    for (int j = 0; j < 32; j += 8) {
        int c = c0 + threadIdx.y + j;
        int t = t0 + threadIdx.x;
        if (t < TDIM) tile[threadIdx.y + j][threadIdx.x] = src[(size_t)c * TDIM + t];
    }
    __syncthreads();
    #pragma unroll
    for (int j = 0; j < 32; j += 8) {
        int t = t0 + threadIdx.y + j;
        int c = c0 + threadIdx.x;
        if (t < TDIM) {
            float x = tile[threadIdx.x][threadIdx.y + j];
            size_t o = (size_t)(b * TDIM + t) * CDIM + c;
            g_E[o]  = x;
            g_Eh[o] = __float2half_rn(x);
        }
    }
}

// ---------------- fused prep: codebook fp16+csq, E row norms, int64 detect ----------------
__global__ void k_prep(const float* __restrict__ cb, const int* __restrict__ w) {
    if (blockIdx.x == 0) {
        __shared__ int any_nonzero;
        if (threadIdx.x == 0) any_nonzero = 0;
        __syncthreads();
        int bad = 0;
        for (int i = threadIdx.x; i < 6000; i += 256)
            if (w[2 * i + 1] != 0) bad = 1;
        if (bad) any_nonzero = 1;   // benign race
        __syncthreads();
        if (threadIdx.x == 0) g_is64 = (any_nonzero == 0) ? 1 : 0;
    }

    int row  = blockIdx.x * 8 + (threadIdx.x >> 5);
    int lane = threadIdx.x & 31;
    if (row < VCNT) {
        const float4* p = (const float4*)(cb + (size_t)row * CDIM);
        __half2* o = (__half2*)(g_Bh + (size_t)row * CDIM);
        float s = 0.f;
        #pragma unroll
        for (int i = lane; i < CDIM / 4; i += 32) {
            float4 q = p[i];
            s += q.x * q.x + q.y * q.y + q.z * q.z + q.w * q.w;
            o[2 * i]     = __floats2half2_rn(q.x, q.y);
            o[2 * i + 1] = __floats2half2_rn(q.z, q.w);
        }
        s = warpSumF(s);
        if (lane == 0) g_csq[row] = s;
    } else {
        int er = row - VCNT;
        if (er < NROWS) {
            const float4* p = (const float4*)(g_E + (size_t)er * CDIM);
            float s = 0.f;
            #pragma unroll
            for (int i = lane; i < CDIM / 4; i += 32) {
                float4 q = p[i];
                s += q.x * q.x + q.y * q.y + q.z * q.z + q.w * q.w;
            }
            s = warpSumF(s);
            if (lane == 0) g_esq[er] = s;
        }
    }
}

// ---------------- fp16 mma.sync GEMM: approx D2 (unchanged, at measured floor) ----------------
__device__ __forceinline__ void load_stage(uint32_t sbase, int m0, int n0, int k0, int tid) {
    #pragma unroll
    for (int it = 0; it < 2; it++) {
        int g = tid + it * 256;          // 0..511: 128 rows x 4 granules of 16B
        int row = g >> 2, gc = g & 3;
        uint32_t off = (uint32_t)(row * ROWB + gc * 16);
        cp16(sbase + off,           g_Eh + (size_t)(m0 + row) * CDIM + k0 + gc * 8);
        cp16(sbase + OPBYTES + off, g_Bh + (size_t)(n0 + row) * CDIM + k0 + gc * 8);
    }
}

__global__ void __launch_bounds__(256, 2) k_gemm_mma() {
    extern __shared__ char smem[];
    uint32_t sb = smem_u32(smem);
    const int tid = threadIdx.x, wid = tid >> 5, lane = tid & 31;
    const int m0 = blockIdx.y * BM, n0 = blockIdx.x * BN;
    const int wm = (wid >> 2) * 64;
    const int wn = (wid & 3) * 32;

    float acc[4][4][4] = {};

    const int lA_row = wm + (lane & 7) + ((lane >> 3) & 1) * 8;
    const int lA_k   = (lane >> 4) * 8;
    const int lB_row = wn + (lane & 7) + (lane >> 4) * 8;
    const int lB_k   = ((lane >> 3) & 1) * 8;

    load_stage(sb + 0 * STG, m0, n0, 0 * BK, tid);
    asm volatile("cp.async.commit_group;" ::: "memory");
    load_stage(sb + 1 * STG, m0, n0, 1 * BK, tid);
    asm volatile("cp.async.commit_group;" ::: "memory");
    load_stage(sb + 2 * STG, m0, n0, 2 * BK, tid);
    asm volatile("cp.async.commit_group;" ::: "memory");

    #pragma unroll
    for (int s = 0; s < NKIT; s++) {
        asm volatile("cp.async.wait_group 2;" ::: "memory");
        __syncthreads();
        if (s + 3 < NKIT) load_stage(sb + (uint32_t)((s + 3) & 3) * STG, m0, n0, (s + 3) * BK, tid);
        asm volatile("cp.async.commit_group;" ::: "memory");

        const uint32_t cur = sb + (uint32_t)(s & 3) * STG;
        #pragma unroll
        for (int kk = 0; kk < 2; kk++) {
            uint32_t aH[4][4], bH[4][2];
            #pragma unroll
            for (int fm = 0; fm < 4; fm++) {
                uint32_t ad = cur + (uint32_t)((lA_row + fm * 16) * ROWB + (kk * 16 + lA_k) * 2);
                LDSM4(aH[fm], ad);
            }
            #pragma unroll
            for (int h = 0; h < 2; h++) {
                uint32_t bd = cur + OPBYTES +
                              (uint32_t)((lB_row + h * 16) * ROWB + (kk * 16 + lB_k) * 2);
                uint32_t t0[4];
                LDSM4(t0, bd);
                bH[2 * h][0] = t0[0]; bH[2 * h][1] = t0[1];
                bH[2 * h + 1][0] = t0[2]; bH[2 * h + 1][1] = t0[3];
            }
            #pragma unroll
            for (int fm = 0; fm < 4; fm++)
                #pragma unroll
                for (int fn = 0; fn < 4; fn++)
                    mma16816(acc[fm][fn], aH[fm], bH[fn]);
        }
    }

    const int g = lane >> 2, l2 = (lane & 3) * 2;
    #pragma unroll
    for (int fm = 0; fm < 4; fm++) {
        #pragma unroll
        for (int half = 0; half < 2; half++) {
            int r = m0 + wm + fm * 16 + g + half * 8;
            if (r < NROWS) {
                float es = g_esq[r];
                float* orow = g_D2 + (size_t)r * VCNT;
                #pragma unroll
                for (int fn = 0; fn < 4; fn++) {
                    int c = n0 + wn + fn * 8 + l2;
                    float2 o;
                    o.x = es + g_csq[c]     - 2.f * acc[fm][fn][half * 2 + 0];
                    o.y = es + g_csq[c + 1] - 2.f * acc[fm][fn][half * 2 + 1];
                    *(float2*)(orow + c) = o;
                }
            }
        }
    }
}

// ---------------- per-row top-K select + exact rescue + loss ----------------
// R9/R15 shape (256 thr x 16 elem, 4-pass float-key radix) with warp-aggregated
// histogram atomics (identical counts, ~8-32x fewer ATOMS instructions).
// Element index mapping: v[4*i + j] holds idx = i*1024 + tid*4 + j.
__global__ void __launch_bounds__(256) k_select(const float* __restrict__ cb,
                                                const int* __restrict__ w) {
    const int n   = blockIdx.x;
    const int tid = threadIdx.x;
    const int wid = tid >> 5, lane = tid & 31;
    const float* row = g_D2 + (size_t)n * VCNT;
    const int code = g_is64 ? w[2 * n] : w[n];
    const float d2c_apx = fmaxf(__ldg(&row[code]), 0.f);

    float    v[16];
    unsigned key[16];
    unsigned lmin = ~0u;
    const float4* row4 = (const float4*)row;
    #pragma unroll
    for (int i = 0; i < 4; i++) {
        float4 f = row4[tid + i * 256];
        v[4 * i + 0] = fmaxf(f.x, 0.f);
        v[4 * i + 1] = fmaxf(f.y, 0.f);
        v[4 * i + 2] = fmaxf(f.z, 0.f);
        v[4 * i + 3] = fmaxf(f.w, 0.f);
    }
    #pragma unroll
    for (int i = 0; i < 16; i++) {
        key[i] = __float_as_uint(v[i]);
        lmin = min(lmin, key[i]);
    }

    __shared__ unsigned s_minkey;
    __shared__ unsigned hist[256];
    __shared__ unsigned s_prefix, s_krem;
    __shared__ int   s_lidx[LCAP];
    __shared__ float s_lval[LCAP];
    __shared__ int   s_lcnt;
    __shared__ float s_dmin, s_dc;
    __shared__ int   s_amin;
    __shared__ float s_wf[8];

    if (tid == 0) {
        s_minkey = ~0u; s_prefix = 0u; s_krem = KSEL;
        s_lcnt = 1; s_lidx[0] = code;         // code always rescued
    }
    __syncthreads();
    atomicMin(&s_minkey, lmin);

    // ---- 4-pass radix select: exact rank-KSEL key of approx d^2 ----
    for (int pass = 0; pass < 4; pass++) {
        int shift = 24 - 8 * pass;
        hist[tid] = 0;
        __syncthreads();
        unsigned pref = s_prefix;
        #pragma unroll
        for (int i = 0; i < 16; i++) {
            bool part = (pass == 0) || (((key[i] ^ pref) >> (shift + 8)) == 0u);
            hist_add(hist, (key[i] >> shift) & 255u, part, lane);
        }
        __syncthreads();
        if (tid < 32) {
            unsigned k = s_krem;
            unsigned loc[8], s0 = 0;
            #pragma unroll
            for (int j = 0; j < 8; j++) { loc[j] = hist[tid * 8 + j]; s0 += loc[j]; }
            unsigned pre = s0;
            #pragma unroll
            for (int o = 1; o < 32; o <<= 1) {
                unsigned t = __shfl_up_sync(0xffffffffu, pre, o);
                if (lane >= o) pre += t;
            }
            unsigned excl = pre - s0;
            if (excl < k && k <= excl + s0) {
                unsigned cum = excl;
                #pragma unroll
                for (int j = 0; j < 8; j++) {
                    if (cum + loc[j] >= k) { s_prefix |= (unsigned)(tid * 8 + j) << shift;
                                             s_krem = k - cum; break; }
                    cum += loc[j];
                }
            }
        }
        __syncthreads();
    }

    const unsigned Tkey = s_prefix;
    const unsigned cbel = KSEL - s_krem;      // strictly-below-threshold count

    // ---- window collect: approx d^2 within DELTA of approx min ----
    const unsigned kwin = __float_as_uint(__uint_as_float(s_minkey) + DELTA);
    #pragma unroll
    for (int i = 0; i < 16; i++) {
        if (key[i] < kwin) {
            int pos = atomicAdd(&s_lcnt, 1);
            if (pos < LCAP) s_lidx[pos] = (i >> 2) * 1024 + tid * 4 + (i & 3);
        }
    }
    __syncthreads();
    const int cnt = min(s_lcnt, LCAP);

    // ---- exact fp32 recompute of rescued candidates (warp per entry) ----
    const float* Er = g_E + (size_t)n * CDIM;
    for (int e = wid; e < cnt; e += 8) {
        int vi = s_lidx[e];
        const float4* A = (const float4*)Er;
        const float4* B = (const float4*)(cb + (size_t)vi * CDIM);
        float d = 0.f;
        #pragma unroll 4
        for (int i = lane; i < CDIM / 4; i += 32) {
            float4 a = A[i], b = B[i];
            d += a.x * b.x + a.y * b.y + a.z * b.z + a.w * b.w;
        }
        d = warpSumF(d);
        if (lane == 0) s_lval[e] = fmaxf(g_esq[n] + g_csq[vi] - 2.f * d, 0.f);
    }
    __syncthreads();

    if (tid == 0) {
        float best = 3.4e38f, dco = 0.f;
        int bidx = 0x7fffffff;
        for (int e = 0; e < cnt; e++) {
            float val = s_lval[e]; int ix = s_lidx[e];
            if (val < best || (val == best && ix < bidx)) { best = val; bidx = ix; }
            if (ix == code) dco = val;
        }
        s_dmin = sqrtf(best);
        s_amin = bidx;
        s_dc   = sqrtf(dco);
    }
    __syncthreads();

    const float dmin = s_dmin;

    // ---- softmax partial sum over keys strictly below threshold ----
    float sw = 0.f;
    #pragma unroll
    for (int i = 0; i < 16; i++)
        if (key[i] < Tkey) sw += __expf(dmin - sqrtf(v[i]));
    sw = warpSumF(sw);
    if (lane == 0) s_wf[wid] = sw;
    __syncthreads();

    if (tid == 0) {
        float swt = 0.f;
        #pragma unroll
        for (int i = 0; i < 8; i++) swt += s_wf[i];

        const unsigned kc = __float_as_uint(d2c_apx);
        float Td = sqrtf(__uint_as_float(Tkey));
        float wT = __expf(dmin - Td);
        float dc = s_dc;
        bool in_topk = (kc <= Tkey);           // exact up to 32-bit key collision
        float S;
        if (in_topk) S = swt + (float)(KSEL - cbel) * wT;
        else         S = swt + (float)(KSEL - 1 - cbel) * wT + __expf(dmin - dc);
        g_row_loss[n]  = dc - dmin + logf(S);
        g_row_match[n] = (s_amin == code) ? 1.f : 0.f;
    }
}

// ---------------- final deterministic reduction ----------------
__global__ void k_finalize(float* __restrict__ out) {
    __shared__ double sl[256], sm[256];
    int tid = threadIdx.x;
    double l = 0.0, m = 0.0;
    for (int i = tid; i < NROWS; i += 256) {
        l += (double)g_row_loss[i];
        m += (double)g_row_match[i];
    }
    sl[tid] = l; sm[tid] = m;
    __syncthreads();
    for (int s = 128; s > 0; s >>= 1) {
        if (tid < s) { sl[tid] += sl[tid + s]; sm[tid] += sm[tid + s]; }
        __syncthreads();
    }
    if (tid == 0) {
        out[0] = (float)(sl[0] / NROWS);
        out[1] = (float)(sm[0] / NROWS);
        out[2] = (float)(sm[0] / NROWS);
        out[3] = 1.0f;
    }
}

// ---------------- launch ----------------
extern "C" void kernel_launch(void* const* d_in, const int* in_sizes, int n_in,
                              void* d_out, int out_size) {
    const float* se    = (const float*)d_in[0];
    const int*   codes = (const int*)d_in[1];
    const float* cb    = (const float*)d_in[2];
    float* out = (float*)d_out;
    (void)in_sizes; (void)n_in; (void)out_size;

    static int attr_done = 0;
    if (!attr_done) {
        cudaFuncSetAttribute(k_gemm_mma, cudaFuncAttributeMaxDynamicSharedMemorySize, SMEM_GEMM);
        attr_done = 1;
    }

    k_transpose<<<dim3((TDIM + 31) / 32, CDIM / 32, BDIMB), dim3(32, 8)>>>(se); // 1
    k_prep<<<(VCNT + NROWS + 7) / 8, 256>>>(cb, codes);                     // 2
    k_gemm_mma<<<dim3(VCNT / BN, MPAD / BM), 256, SMEM_GEMM>>>();           // 3
    k_select<<<NROWS, 256>>>(cb, codes);                                    // 4 <- ncu samples here
    k_finalize<<<1, 256>>>(out);                                            // 5
}

// round 17
// speedup vs baseline: 1.5926x; 1.5926x over previous
#include <cuda_runtime.h>
#include <cuda_fp16.h>
#include <cstdint>

#define NROWS 12000     // B*T = 8*1500
#define MPAD  12032     // 94 * 128
#define BDIMB 8
#define TDIM  1500
#define CDIM  512
#define VCNT  4096
#define KSEL  100
#define DELTA 0.25f     // exact-rescue window on approx d^2 (~25 sigma of fp16 GEMM error)
#define LCAP  32

// ---- mma.sync GEMM tiling (fp16 single-term) ----
#define BM 128
#define BN 128
#define BK 32
#define ROWB 80                       // smem leading dim bytes (40 halfs), ldmatrix conflict-free
#define OPBYTES (128 * ROWB)          // 10240 per operand per stage
#define STG (2 * OPBYTES)             // 20480 (A, B)
#define NSTAGE 4
#define SMEM_GEMM (NSTAGE * STG)      // 81920 -> 2 CTAs/SM
#define NKIT (CDIM / BK)              // 16

// ---------------- scratch (device globals: no allocations allowed) ----------------
__device__ __align__(16) float g_E[(size_t)NROWS * CDIM];      // fp32 tokens x C (exact path)
__device__ __align__(16) __half g_Eh[(size_t)MPAD * CDIM];     // rows >= NROWS stay 0
__device__ __align__(16) __half g_Bh[(size_t)VCNT * CDIM];
__device__ float g_esq[NROWS];
__device__ float g_csq[VCNT];
__device__ __align__(16) float g_D2[(size_t)NROWS * VCNT];     // 196.6 MB approx d^2
__device__ int   g_is64;
__device__ float g_row_loss[NROWS];
__device__ float g_row_match[NROWS];

// ---------------- helpers ----------------
__device__ __forceinline__ float warpSumF(float v) {
    #pragma unroll
    for (int o = 16; o > 0; o >>= 1) v += __shfl_down_sync(0xffffffffu, v, o);
    return v;
}
__device__ __forceinline__ uint32_t smem_u32(const void* p) {
    uint32_t a;
    asm("{ .reg .u64 t; cvta.to.shared.u64 t, %1; cvt.u32.u64 %0, t; }" : "=r"(a) : "l"(p));
    return a;
}
__device__ __forceinline__ void cp16(uint32_t dst, const void* src) {
    asm volatile("cp.async.cg.shared.global [%0], [%1], 16;" :: "r"(dst), "l"(src));
}
#define LDSM4(r, a) \
    asm volatile("ldmatrix.sync.aligned.m8n8.x4.shared.b16 {%0,%1,%2,%3}, [%4];" \
        : "=r"((r)[0]), "=r"((r)[1]), "=r"((r)[2]), "=r"((r)[3]) : "r"(a))

__device__ __forceinline__ void mma16816(float* c, const uint32_t* a, const uint32_t* b) {
    asm volatile(
        "mma.sync.aligned.m16n8k16.row.col.f32.f16.f16.f32 "
        "{%0,%1,%2,%3}, {%4,%5,%6,%7}, {%8,%9}, {%0,%1,%2,%3};"
        : "+f"(c[0]), "+f"(c[1]), "+f"(c[2]), "+f"(c[3])
        : "r"(a[0]), "r"(a[1]), "r"(a[2]), "r"(a[3]), "r"(b[0]), "r"(b[1]));
}

// ---------------- transpose student_emb (B,C,T) -> g_E fp32 + g_Eh fp16 ----------------
__global__ void k_transpose(const float* __restrict__ se) {
    __shared__ float tile[32][33];
    int b  = blockIdx.z;
    int t0 = blockIdx.x * 32;
    int c0 = blockIdx.y * 32;
    const float* src = se + (size_t)b * CDIM * TDIM;
    #pragma unroll
    for (int j = 0; j < 32; j += 8) {
        int c = c0 + threadIdx.y + j;
        int t = t0 + threadIdx.x;
        if (t < TDIM) tile[threadIdx.y + j][threadIdx.x] = src[(size_t)c * TDIM + t];
    }
    __syncthreads();
    #pragma unroll
    for (int j = 0; j < 32; j += 8) {
        int t = t0 + threadIdx.y + j;
        int c = c0 + threadIdx.x;
        if (t < TDIM) {
            float x = tile[threadIdx.x][threadIdx.y + j];
            size_t o = (size_t)(b * TDIM + t) * CDIM + c;
            g_E[o]  = x;
            g_Eh[o] = __float2half_rn(x);
        }
    }
}

// ---------------- fused prep: codebook fp16+csq, E row norms, int64 detect ----------------
__global__ void k_prep(const float* __restrict__ cb, const int* __restrict__ w) {
    if (blockIdx.x == 0) {
        __shared__ int any_nonzero;
        if (threadIdx.x == 0) any_nonzero = 0;
        __syncthreads();
        int bad = 0;
        for (int i = threadIdx.x; i < 6000; i += 256)
            if (w[2 * i + 1] != 0) bad = 1;
        if (bad) any_nonzero = 1;   // benign race
        __syncthreads();
        if (threadIdx.x == 0) g_is64 = (any_nonzero == 0) ? 1 : 0;
    }

    int row  = blockIdx.x * 8 + (threadIdx.x >> 5);
    int lane = threadIdx.x & 31;
    if (row < VCNT) {
        const float4* p = (const float4*)(cb + (size_t)row * CDIM);
        __half2* o = (__half2*)(g_Bh + (size_t)row * CDIM);
        float s = 0.f;
        #pragma unroll
        for (int i = lane; i < CDIM / 4; i += 32) {
            float4 q = p[i];
            s += q.x * q.x + q.y * q.y + q.z * q.z + q.w * q.w;
            o[2 * i]     = __floats2half2_rn(q.x, q.y);
            o[2 * i + 1] = __floats2half2_rn(q.z, q.w);
        }
        s = warpSumF(s);
        if (lane == 0) g_csq[row] = s;
    } else {
        int er = row - VCNT;
        if (er < NROWS) {
            const float4* p = (const float4*)(g_E + (size_t)er * CDIM);
            float s = 0.f;
            #pragma unroll
            for (int i = lane; i < CDIM / 4; i += 32) {
                float4 q = p[i];
                s += q.x * q.x + q.y * q.y + q.z * q.z + q.w * q.w;
            }
            s = warpSumF(s);
            if (lane == 0) g_esq[er] = s;
        }
    }
}

// ---------------- fp16 mma.sync GEMM: approx D2 (unchanged, at measured floor) ----------------
__device__ __forceinline__ void load_stage(uint32_t sbase, int m0, int n0, int k0, int tid) {
    #pragma unroll
    for (int it = 0; it < 2; it++) {
        int g = tid + it * 256;          // 0..511: 128 rows x 4 granules of 16B
        int row = g >> 2, gc = g & 3;
        uint32_t off = (uint32_t)(row * ROWB + gc * 16);
        cp16(sbase + off,           g_Eh + (size_t)(m0 + row) * CDIM + k0 + gc * 8);
        cp16(sbase + OPBYTES + off, g_Bh + (size_t)(n0 + row) * CDIM + k0 + gc * 8);
    }
}

__global__ void __launch_bounds__(256, 2) k_gemm_mma() {
    extern __shared__ char smem[];
    uint32_t sb = smem_u32(smem);
    const int tid = threadIdx.x, wid = tid >> 5, lane = tid & 31;
    const int m0 = blockIdx.y * BM, n0 = blockIdx.x * BN;
    const int wm = (wid >> 2) * 64;
    const int wn = (wid & 3) * 32;

    float acc[4][4][4] = {};

    const int lA_row = wm + (lane & 7) + ((lane >> 3) & 1) * 8;
    const int lA_k   = (lane >> 4) * 8;
    const int lB_row = wn + (lane & 7) + (lane >> 4) * 8;
    const int lB_k   = ((lane >> 3) & 1) * 8;

    load_stage(sb + 0 * STG, m0, n0, 0 * BK, tid);
    asm volatile("cp.async.commit_group;" ::: "memory");
    load_stage(sb + 1 * STG, m0, n0, 1 * BK, tid);
    asm volatile("cp.async.commit_group;" ::: "memory");
    load_stage(sb + 2 * STG, m0, n0, 2 * BK, tid);
    asm volatile("cp.async.commit_group;" ::: "memory");

    #pragma unroll
    for (int s = 0; s < NKIT; s++) {
        asm volatile("cp.async.wait_group 2;" ::: "memory");
        __syncthreads();
        if (s + 3 < NKIT) load_stage(sb + (uint32_t)((s + 3) & 3) * STG, m0, n0, (s + 3) * BK, tid);
        asm volatile("cp.async.commit_group;" ::: "memory");

        const uint32_t cur = sb + (uint32_t)(s & 3) * STG;
        #pragma unroll
        for (int kk = 0; kk < 2; kk++) {
            uint32_t aH[4][4], bH[4][2];
            #pragma unroll
            for (int fm = 0; fm < 4; fm++) {
                uint32_t ad = cur + (uint32_t)((lA_row + fm * 16) * ROWB + (kk * 16 + lA_k) * 2);
                LDSM4(aH[fm], ad);
            }
            #pragma unroll
            for (int h = 0; h < 2; h++) {
                uint32_t bd = cur + OPBYTES +
                              (uint32_t)((lB_row + h * 16) * ROWB + (kk * 16 + lB_k) * 2);
                uint32_t t0[4];
                LDSM4(t0, bd);
                bH[2 * h][0] = t0[0]; bH[2 * h][1] = t0[1];
                bH[2 * h + 1][0] = t0[2]; bH[2 * h + 1][1] = t0[3];
            }
            #pragma unroll
            for (int fm = 0; fm < 4; fm++)
                #pragma unroll
                for (int fn = 0; fn < 4; fn++)
                    mma16816(acc[fm][fn], aH[fm], bH[fn]);
        }
    }

    const int g = lane >> 2, l2 = (lane & 3) * 2;
    #pragma unroll
    for (int fm = 0; fm < 4; fm++) {
        #pragma unroll
        for (int half = 0; half < 2; half++) {
            int r = m0 + wm + fm * 16 + g + half * 8;
            if (r < NROWS) {
                float es = g_esq[r];
                float* orow = g_D2 + (size_t)r * VCNT;
                #pragma unroll
                for (int fn = 0; fn < 4; fn++) {
                    int c = n0 + wn + fn * 8 + l2;
                    float2 o;
                    o.x = es + g_csq[c]     - 2.f * acc[fm][fn][half * 2 + 0];
                    o.y = es + g_csq[c + 1] - 2.f * acc[fm][fn][half * 2 + 1];
                    *(float2*)(orow + c) = o;
                }
            }
        }
    }
}

// ---------------- per-row top-K select + exact rescue + loss ----------------
// R15 core (256 thr x 16 elem, 4-pass float-key radix, plain atomics) with
// thread-local TWO-BIN aggregation for pass 0: key exponents cluster into 1-2
// adjacent top-byte bins, so each thread issues 1-2 atomics instead of 16.
// Counts are bit-identical (fallback path covers the general case).
// Element index mapping: v[4*i + j] holds idx = i*1024 + tid*4 + j.
__global__ void __launch_bounds__(256) k_select(const float* __restrict__ cb,
                                                const int* __restrict__ w) {
    const int n   = blockIdx.x;
    const int tid = threadIdx.x;
    const int wid = tid >> 5, lane = tid & 31;
    const float* row = g_D2 + (size_t)n * VCNT;
    const int code = g_is64 ? w[2 * n] : w[n];
    const float d2c_apx = fmaxf(__ldg(&row[code]), 0.f);

    float    v[16];
    unsigned key[16];
    unsigned lmin = ~0u;
    const float4* row4 = (const float4*)row;
    #pragma unroll
    for (int i = 0; i < 4; i++) {
        float4 f = row4[tid + i * 256];
        v[4 * i + 0] = fmaxf(f.x, 0.f);
        v[4 * i + 1] = fmaxf(f.y, 0.f);
        v[4 * i + 2] = fmaxf(f.z, 0.f);
        v[4 * i + 3] = fmaxf(f.w, 0.f);
    }
    #pragma unroll
    for (int i = 0; i < 16; i++) {
        key[i] = __float_as_uint(v[i]);
        lmin = min(lmin, key[i]);
    }

    __shared__ unsigned s_minkey;
    __shared__ unsigned hist[256];
    __shared__ unsigned s_prefix, s_krem;
    __shared__ int   s_lidx[LCAP];
    __shared__ float s_lval[LCAP];
    __shared__ int   s_lcnt;
    __shared__ float s_dmin, s_dc;
    __shared__ int   s_amin;
    __shared__ float s_wf[8];

    if (tid == 0) {
        s_minkey = ~0u; s_prefix = 0u; s_krem = KSEL;
        s_lcnt = 1; s_lidx[0] = code;         // code always rescued
    }
    hist[tid] = 0;
    __syncthreads();
    atomicMin(&s_minkey, lmin);

    // ---- pass 0: top-byte histogram with thread-local two-bin aggregation ----
    {
        unsigned bmin = key[0] >> 24, bmax = bmin;
        #pragma unroll
        for (int i = 1; i < 16; i++) {
            unsigned b = key[i] >> 24;
            bmin = min(bmin, b);
            bmax = max(bmax, b);
        }
        if (bmax - bmin <= 1u) {              // common case: 1-2 adjacent bins
            int c0 = 0;
            #pragma unroll
            for (int i = 0; i < 16; i++) c0 += ((key[i] >> 24) == bmin);
            atomicAdd(&hist[bmin], (unsigned)c0);
            if (bmax != bmin) atomicAdd(&hist[bmax], (unsigned)(16 - c0));
        } else {                               // rare fallback: exact same counts
            #pragma unroll
            for (int i = 0; i < 16; i++) atomicAdd(&hist[key[i] >> 24], 1u);
        }
    }
    __syncthreads();

    // ---- 4-pass radix scan/select (pass 0 hist already built) ----
    for (int pass = 0; pass < 4; pass++) {
        int shift = 24 - 8 * pass;
        if (pass > 0) {
            hist[tid] = 0;
            __syncthreads();
            unsigned pref = s_prefix;
            #pragma unroll
            for (int i = 0; i < 16; i++) {
                bool part = ((key[i] ^ pref) >> (shift + 8)) == 0u;
                if (part) atomicAdd(&hist[(key[i] >> shift) & 255u], 1u);
            }
            __syncthreads();
        }
        if (tid < 32) {
            unsigned k = s_krem;
            unsigned loc[8], s0 = 0;
            #pragma unroll
            for (int j = 0; j < 8; j++) { loc[j] = hist[tid * 8 + j]; s0 += loc[j]; }
            unsigned pre = s0;
            #pragma unroll
            for (int o = 1; o < 32; o <<= 1) {
                unsigned t = __shfl_up_sync(0xffffffffu, pre, o);
                if (lane >= o) pre += t;
            }
            unsigned excl = pre - s0;
            if (excl < k && k <= excl + s0) {
                unsigned cum = excl;
                #pragma unroll
                for (int j = 0; j < 8; j++) {
                    if (cum + loc[j] >= k) { s_prefix |= (unsigned)(tid * 8 + j) << shift;
                                             s_krem = k - cum; break; }
                    cum += loc[j];
                }
            }
        }
        __syncthreads();
    }

    const unsigned Tkey = s_prefix;
    const unsigned cbel = KSEL - s_krem;      // strictly-below-threshold count

    // ---- window collect: approx d^2 within DELTA of approx min ----
    const unsigned kwin = __float_as_uint(__uint_as_float(s_minkey) + DELTA);
    #pragma unroll
    for (int i = 0; i < 16; i++) {
        if (key[i] < kwin) {
            int pos = atomicAdd(&s_lcnt, 1);
            if (pos < LCAP) s_lidx[pos] = (i >> 2) * 1024 + tid * 4 + (i & 3);
        }
    }
    __syncthreads();
    const int cnt = min(s_lcnt, LCAP);

    // ---- exact fp32 recompute of rescued candidates (warp per entry) ----
    const float* Er = g_E + (size_t)n * CDIM;
    for (int e = wid; e < cnt; e += 8) {
        int vi = s_lidx[e];
        const float4* A = (const float4*)Er;
        const float4* B = (const float4*)(cb + (size_t)vi * CDIM);
        float d = 0.f;
        #pragma unroll 4
        for (int i = lane; i < CDIM / 4; i += 32) {
            float4 a = A[i], b = B[i];
            d += a.x * b.x + a.y * b.y + a.z * b.z + a.w * b.w;
        }
        d = warpSumF(d);
        if (lane == 0) s_lval[e] = fmaxf(g_esq[n] + g_csq[vi] - 2.f * d, 0.f);
    }
    __syncthreads();

    if (tid == 0) {
        float best = 3.4e38f, dco = 0.f;
        int bidx = 0x7fffffff;
        for (int e = 0; e < cnt; e++) {
            float val = s_lval[e]; int ix = s_lidx[e];
            if (val < best || (val == best && ix < bidx)) { best = val; bidx = ix; }
            if (ix == code) dco = val;
        }
        s_dmin = sqrtf(best);
        s_amin = bidx;
        s_dc   = sqrtf(dco);
    }
    __syncthreads();

    const float dmin = s_dmin;

    // ---- softmax partial sum over keys strictly below threshold ----
    float sw = 0.f;
    #pragma unroll
    for (int i = 0; i < 16; i++)
        if (key[i] < Tkey) sw += __expf(dmin - sqrtf(v[i]));
    sw = warpSumF(sw);
    if (lane == 0) s_wf[wid] = sw;
    __syncthreads();

    if (tid == 0) {
        float swt = 0.f;
        #pragma unroll
        for (int i = 0; i < 8; i++) swt += s_wf[i];

        const unsigned kc = __float_as_uint(d2c_apx);
        float Td = sqrtf(__uint_as_float(Tkey));
        float wT = __expf(dmin - Td);
        float dc = s_dc;
        bool in_topk = (kc <= Tkey);           // exact up to 32-bit key collision
        float S;
        if (in_topk) S = swt + (float)(KSEL - cbel) * wT;
        else         S = swt + (float)(KSEL - 1 - cbel) * wT + __expf(dmin - dc);
        g_row_loss[n]  = dc - dmin + logf(S);
        g_row_match[n] = (s_amin == code) ? 1.f : 0.f;
    }
}

// ---------------- final deterministic reduction ----------------
__global__ void k_finalize(float* __restrict__ out) {
    __shared__ double sl[256], sm[256];
    int tid = threadIdx.x;
    double l = 0.0, m = 0.0;
    for (int i = tid; i < NROWS; i += 256) {
        l += (double)g_row_loss[i];
        m += (double)g_row_match[i];
    }
    sl[tid] = l; sm[tid] = m;
    __syncthreads();
    for (int s = 128; s > 0; s >>= 1) {
        if (tid < s) { sl[tid] += sl[tid + s]; sm[tid] += sm[tid + s]; }
        __syncthreads();
    }
    if (tid == 0) {
        out[0] = (float)(sl[0] / NROWS);
        out[1] = (float)(sm[0] / NROWS);
        out[2] = (float)(sm[0] / NROWS);
        out[3] = 1.0f;
    }
}

// ---------------- launch ----------------
extern "C" void kernel_launch(void* const* d_in, const int* in_sizes, int n_in,
                              void* d_out, int out_size) {
    const float* se    = (const float*)d_in[0];
    const int*   codes = (const int*)d_in[1];
    const float* cb    = (const float*)d_in[2];
    float* out = (float*)d_out;
    (void)in_sizes; (void)n_in; (void)out_size;

    static int attr_done = 0;
    if (!attr_done) {
        cudaFuncSetAttribute(k_gemm_mma, cudaFuncAttributeMaxDynamicSharedMemorySize, SMEM_GEMM);
        attr_done = 1;
    }

    k_transpose<<<dim3((TDIM + 31) / 32, CDIM / 32, BDIMB), dim3(32, 8)>>>(se); // 1
    k_prep<<<(VCNT + NROWS + 7) / 8, 256>>>(cb, codes);                     // 2
    k_gemm_mma<<<dim3(VCNT / BN, MPAD / BM), 256, SMEM_GEMM>>>();           // 3
    k_select<<<NROWS, 256>>>(cb, codes);                                    // 4 <- ncu samples here
    k_finalize<<<1, 256>>>(out);                                            // 5
}